// round 15
// baseline (speedup 1.0000x reference)
#include <cuda_runtime.h>
#include <math.h>

#define EPSF 1e-8f
#define BB 64
#define NN 1024
#define WW 128

#define NBLK 740                 // 5 blocks/SM x 148 SMs; co-residency guaranteed
#define SIM_ITEMS 2048           // 32 rows each
#define LINK_ITEMS 32768         // 2 rows each
#define TOTAL_ITEMS (SIM_ITEMS + LINK_ITEMS)

__device__ float        g_e[BB * NN];   // exp(beta * cosine)
__device__ float4       g_scal[BB];     // {wg*ag, wg*(1-ag)/esum, 1-wsum, 0}
__device__ unsigned int g_cnt[BB];      // 0 -> 32 (sim) -> 544 (link) -> reset 0
__device__ int          g_flag[BB];     // scal-ready flag, reset by last link item

__device__ __forceinline__ float warp_sum(float v) {
#pragma unroll
    for (int o = 16; o; o >>= 1) v += __shfl_xor_sync(0xffffffffu, v, o);
    return v;
}

__global__ __launch_bounds__(256, 5) void wh_fused_kernel(
    const float* __restrict__ w_key, const float* __restrict__ w_beta,
    const float* __restrict__ memory, float* __restrict__ out_mem,
    const float* __restrict__ a_gate, const float* __restrict__ w_gate,
    const float* __restrict__ alloc, const float* __restrict__ L,
    const float* __restrict__ p, float* __restrict__ out_link,
    float* __restrict__ out_w, float* __restrict__ out_prec)
{
    const int t = threadIdx.x;
    const int lane = t & 31;
    const int warp = t >> 5;
    const unsigned FULL = 0xffffffffu;

    __shared__ int   s_last;
    __shared__ float s_e[8], s_a[8];

    for (int w = blockIdx.x; w < TOTAL_ITEMS; w += NBLK) {
        if (w < SIM_ITEMS) {
            // ================= SIM item: 32 rows (4/warp) =================
            const size_t row0 = ((size_t)w * 8 + warp) * 4;
            const int b = w >> 5;

            const float4 k4 = __ldg(reinterpret_cast<const float4*>(w_key + b * WW) + lane);
            float ks = k4.x * k4.x + k4.y * k4.y + k4.z * k4.z + k4.w * k4.w;
            ks = warp_sum(ks);
            const float knorm = sqrtf(ks) + EPSF;

            const float bx = __ldg(w_beta + b);
            const float beta = 1.f + (bx > 20.f ? bx : log1pf(expf(bx)));

            float4 m[4];
#pragma unroll
            for (int r = 0; r < 4; r++)
                m[r] = reinterpret_cast<const float4*>(memory + (row0 + r) * WW)[lane];

#pragma unroll
            for (int r = 0; r < 4; r++)
                __stcs(reinterpret_cast<float4*>(out_mem + (row0 + r) * WW) + lane, m[r]);

            float dot[4], sq[4];
#pragma unroll
            for (int r = 0; r < 4; r++) {
                dot[r] = m[r].x * k4.x + m[r].y * k4.y + m[r].z * k4.z + m[r].w * k4.w;
                sq[r]  = m[r].x * m[r].x + m[r].y * m[r].y + m[r].z * m[r].z + m[r].w * m[r].w;
            }

            // tree-merge reduction: 8 values, 17 SHFLs
            const bool lo16 = (lane & 16) == 0;
            float A[4];
#pragma unroll
            for (int r = 0; r < 4; r++) {
                float dx = __shfl_xor_sync(FULL, dot[r], 16);
                float sx = __shfl_xor_sync(FULL, sq[r], 16);
                A[r] = lo16 ? (dot[r] + dx) : (sq[r] + sx);
            }
            const bool lo8 = (lane & 8) == 0;
            float a0 = __shfl_xor_sync(FULL, A[0], 8);
            float a1 = __shfl_xor_sync(FULL, A[1], 8);
            float B0 = lo8 ? (A[0] + a0) : (A[1] + a1);
            float a2 = __shfl_xor_sync(FULL, A[2], 8);
            float a3 = __shfl_xor_sync(FULL, A[3], 8);
            float B1 = lo8 ? (A[2] + a2) : (A[3] + a3);
            const bool lo4 = (lane & 4) == 0;
            float b0 = __shfl_xor_sync(FULL, B0, 4);
            float b1 = __shfl_xor_sync(FULL, B1, 4);
            float C = lo4 ? (B0 + b0) : (B1 + b1);
            C += __shfl_xor_sync(FULL, C, 2);
            C += __shfl_xor_sync(FULL, C, 1);
            const float sqv = __shfl_xor_sync(FULL, C, 16);

            if ((lane & 19) == 0) {
                const int r = ((lane & 4) ? 2 : 0) + ((lane & 8) ? 1 : 0);
                const float sim = beta * C / ((sqrtf(sqv) + EPSF) * knorm);
                g_e[row0 + r] = expf(sim);
            }

            // last-item-per-batch scalar epilogue
            __syncthreads();
            if (t == 0) {
                __threadfence();                       // release g_e writes
                unsigned prev = atomicAdd(&g_cnt[b], 1u);
                s_last = (prev == 31u);
            }
            __syncthreads();
            if (s_last) {
                __threadfence();                       // acquire others' g_e
                const float4 e4 = __ldcg(reinterpret_cast<const float4*>(g_e + (size_t)b * NN) + t);
                const float4 av = __ldg(reinterpret_cast<const float4*>(alloc + (size_t)b * NN) + t);
                float se = e4.x + e4.y + e4.z + e4.w;
                float sa = av.x + av.y + av.z + av.w;
                se = warp_sum(se);
                sa = warp_sum(sa);
                if (lane == 0) { s_e[warp] = se; s_a[warp] = sa; }
                __syncthreads();
                if (t == 0) {
                    float esum = 0.f, asum = 0.f;
#pragma unroll
                    for (int i = 0; i < 8; i++) { esum += s_e[i]; asum += s_a[i]; }
                    const float wg = 1.f / (1.f + expf(-w_gate[b]));
                    const float ag = 1.f / (1.f + expf(-a_gate[b]));
                    const float s0 = wg * ag;
                    const float s1 = wg * (1.f - ag) / esum;
                    const float wsum = wg * (ag * asum + (1.f - ag));
                    g_scal[b] = make_float4(s0, s1, 1.f - wsum, 0.f);
                    __threadfence();                   // release g_scal
                    atomicExch(&g_flag[b], 1);
                }
            }
        } else {
            // ================= LINK item: 2 rows =================
            const int li = w - SIM_ITEMS;
            const size_t row0 = (size_t)li * 2;
            const int b = (int)(row0 >> 10);
            const int i0 = (int)(row0 & 1023);
            const int j4 = t;

            // prefetch the heavy stream + broadcasts BEFORE the wait
            const float4 l0 = __ldcs(reinterpret_cast<const float4*>(L) + row0 * 256 + j4);
            const float4 l1 = __ldcs(reinterpret_cast<const float4*>(L) + (row0 + 1) * 256 + j4);
            const float4 pj = __ldg(reinterpret_cast<const float4*>(p) + (size_t)b * 256 + j4);
            const float4 aj = __ldg(reinterpret_cast<const float4*>(alloc) + (size_t)b * 256 + j4);
            const float ai0 = __ldg(alloc + row0);
            const float ai1 = __ldg(alloc + row0 + 1);

            if (t == 0) {
                while (atomicAdd(&g_flag[b], 0) == 0) __nanosleep(64);
            }
            __syncthreads();
            __threadfence();                           // acquire g_scal/g_e

            const float4 sc = __ldcg(reinterpret_cast<const float4*>(&g_scal[b]));
            const float4 ej = __ldcg(reinterpret_cast<const float4*>(g_e + (size_t)b * NN) + j4);
            const float ei0 = __ldcg(g_e + row0);
            const float ei1 = __ldcg(g_e + row0 + 1);

            const float wi0 = sc.x * ai0 + sc.y * ei0;
            const float wi1 = sc.x * ai1 + sc.y * ei1;

            float4 wj;
            wj.x = sc.x * aj.x + sc.y * ej.x;
            wj.y = sc.x * aj.y + sc.y * ej.y;
            wj.z = sc.x * aj.z + sc.y * ej.z;
            wj.w = sc.x * aj.w + sc.y * ej.w;

            float4 o0, o1;
            o0.x = (1.f - wi0 - wj.x) * l0.x + wi0 * pj.x;
            o0.y = (1.f - wi0 - wj.y) * l0.y + wi0 * pj.y;
            o0.z = (1.f - wi0 - wj.z) * l0.z + wi0 * pj.z;
            o0.w = (1.f - wi0 - wj.w) * l0.w + wi0 * pj.w;
            o1.x = (1.f - wi1 - wj.x) * l1.x + wi1 * pj.x;
            o1.y = (1.f - wi1 - wj.y) * l1.y + wi1 * pj.y;
            o1.z = (1.f - wi1 - wj.z) * l1.z + wi1 * pj.z;
            o1.w = (1.f - wi1 - wj.w) * l1.w + wi1 * pj.w;

            if (j4 == (i0 >> 2))       ((float*)&o0)[i0 & 3]       = 0.f;
            if (j4 == ((i0 + 1) >> 2)) ((float*)&o1)[(i0 + 1) & 3] = 0.f;

            __stcs(reinterpret_cast<float4*>(out_link) + row0 * 256 + j4, o0);
            __stcs(reinterpret_cast<float4*>(out_link) + (row0 + 1) * 256 + j4, o1);

            if (i0 == 0) {
                reinterpret_cast<float4*>(out_w + (size_t)b * NN)[j4] = wj;
                float4 pn;
                pn.x = sc.z * pj.x + wj.x;
                pn.y = sc.z * pj.y + wj.y;
                pn.z = sc.z * pj.z + wj.z;
                pn.w = sc.z * pj.w + wj.w;
                reinterpret_cast<float4*>(out_prec + (size_t)b * NN)[j4] = pn;
            }

            __syncthreads();
            if (t == 0) {
                unsigned prev = atomicAdd(&g_cnt[b], 1u);
                if (prev == 543u) {        // 32 sim + 512 link items all done
                    g_cnt[b]  = 0u;        // self-restore for next graph replay
                    g_flag[b] = 0;
                }
            }
        }
    }
}

extern "C" void kernel_launch(void* const* d_in, const int* in_sizes, int n_in,
                              void* d_out, int out_size)
{
    const float* w_key  = (const float*)d_in[0];
    const float* w_beta = (const float*)d_in[1];
    // d_in[2] = e_vector (unused), d_in[3] = w_vector (unused)
    const float* a_gate = (const float*)d_in[4];
    const float* w_gate = (const float*)d_in[5];
    const float* alloc  = (const float*)d_in[6];
    const float* memory = (const float*)d_in[7];
    const float* linkm  = (const float*)d_in[8];
    const float* prec   = (const float*)d_in[9];

    float* out = (float*)d_out;
    float* out_w    = out;                                   // B*N
    float* out_mem  = out + (size_t)BB * NN;                 // B*N*W
    float* out_link = out_mem + (size_t)BB * NN * WW;        // B*N*N
    float* out_prec = out_link + (size_t)BB * NN * NN;       // B*N

    wh_fused_kernel<<<NBLK, 256>>>(w_key, w_beta, memory, out_mem,
                                   a_gate, w_gate, alloc, linkm, prec,
                                   out_link, out_w, out_prec);
}

// round 16
// speedup vs baseline: 1.3953x; 1.3953x over previous
#include <cuda_runtime.h>
#include <math.h>

#define EPSF 1e-8f
#define BB 64
#define NN 1024
#define WW 128

__device__ float  g_e[BB * NN];    // scratch: exp(beta * cosine)
__device__ float4 g_scal[BB];      // per-batch {wg*ag, wg*(1-ag)/esum, 1-wsum, 0}

__device__ __forceinline__ float warp_sum(float v) {
#pragma unroll
    for (int o = 16; o; o >>= 1) v += __shfl_xor_sync(0xffffffffu, v, o);
    return v;
}

#define SIM_BLOCKS 1024
#define SIM_ITEMS  2048

// Phase 1: e = exp(beta * cosine) + fused memory passthrough.
// Grid-stride: 1024 blocks x 2 items (item = 32 rows, 4 rows/warp).
// One full wave at 8 blocks/SM -> no wave-quantization tail.
__global__ __launch_bounds__(256) void wh_sim_kernel(
    const float* __restrict__ w_key, const float* __restrict__ w_beta,
    const float* __restrict__ memory, float* __restrict__ out_mem)
{
    const int t = threadIdx.x;
    const int lane = t & 31;
    const int warp = t >> 5;
    const unsigned FULL = 0xffffffffu;

#pragma unroll 1
    for (int item = blockIdx.x; item < SIM_ITEMS; item += SIM_BLOCKS) {
        const size_t row0 = ((size_t)item * 8 + warp) * 4;  // first of 4 rows
        const int b = item >> 5;                            // 32 items per batch

        const float4 k4 = __ldg(reinterpret_cast<const float4*>(w_key + b * WW) + lane);
        float ks = k4.x * k4.x + k4.y * k4.y + k4.z * k4.z + k4.w * k4.w;
        ks = warp_sum(ks);
        const float knorm = sqrtf(ks) + EPSF;

        const float bx = __ldg(w_beta + b);
        const float beta = 1.f + (bx > 20.f ? bx : log1pf(expf(bx)));

        float4 m[4];
#pragma unroll
        for (int r = 0; r < 4; r++)
            m[r] = reinterpret_cast<const float4*>(memory + (row0 + r) * WW)[lane];

        // fused passthrough copy (stores retire independently)
#pragma unroll
        for (int r = 0; r < 4; r++)
            __stcs(reinterpret_cast<float4*>(out_mem + (row0 + r) * WW) + lane, m[r]);

        float dot[4], sq[4];
#pragma unroll
        for (int r = 0; r < 4; r++) {
            dot[r] = m[r].x * k4.x + m[r].y * k4.y + m[r].z * k4.z + m[r].w * k4.w;
            sq[r]  = m[r].x * m[r].x + m[r].y * m[r].y + m[r].z * m[r].z + m[r].w * m[r].w;
        }

        // ---- tree-merge reduction: 8 values -> lane-indexed sums (17 SHFLs) ----
        const bool lo16 = (lane & 16) == 0;
        float A[4];
#pragma unroll
        for (int r = 0; r < 4; r++) {
            float dx = __shfl_xor_sync(FULL, dot[r], 16);
            float sx = __shfl_xor_sync(FULL, sq[r], 16);
            A[r] = lo16 ? (dot[r] + dx) : (sq[r] + sx);
        }
        const bool lo8 = (lane & 8) == 0;
        float a0 = __shfl_xor_sync(FULL, A[0], 8);
        float a1 = __shfl_xor_sync(FULL, A[1], 8);
        float B0 = lo8 ? (A[0] + a0) : (A[1] + a1);
        float a2 = __shfl_xor_sync(FULL, A[2], 8);
        float a3 = __shfl_xor_sync(FULL, A[3], 8);
        float B1 = lo8 ? (A[2] + a2) : (A[3] + a3);
        const bool lo4 = (lane & 4) == 0;
        float b0 = __shfl_xor_sync(FULL, B0, 4);
        float b1 = __shfl_xor_sync(FULL, B1, 4);
        float C = lo4 ? (B0 + b0) : (B1 + b1);
        C += __shfl_xor_sync(FULL, C, 2);
        C += __shfl_xor_sync(FULL, C, 1);
        const float sqv = __shfl_xor_sync(FULL, C, 16);

        // lanes 0,4,8,12 hold dot for r = ((lane&4)?2:0) + ((lane&8)?1:0)
        if ((lane & 19) == 0) {
            const int r = ((lane & 4) ? 2 : 0) + ((lane & 8) ? 1 : 0);
            const float sim = beta * C / ((sqrtf(sqv) + EPSF) * knorm);
            g_e[row0 + r] = expf(sim);   // no-max softmax numerator (|sim| small)
        }
    }
}

// Phase 2: per-batch scalar reduction. 64 blocks x 256 threads.
// Emits {wg*ag, wg*(1-ag)/esum, 1 - wsum} with wsum = wg*(ag*S_alloc + (1-ag)).
__global__ __launch_bounds__(256) void wh_scal_kernel(
    const float* __restrict__ a_gate, const float* __restrict__ w_gate,
    const float* __restrict__ alloc)
{
    const int b = blockIdx.x;
    const int t = threadIdx.x;
    const int lane = t & 31;
    const int warp = t >> 5;
    __shared__ float s_e[8], s_a[8];

    // independent inputs before grid-dep sync
    const float wg = 1.f / (1.f + expf(-w_gate[b]));
    const float ag = 1.f / (1.f + expf(-a_gate[b]));
    const float4 av = __ldg(reinterpret_cast<const float4*>(alloc + (size_t)b * NN) + t);
    float sa = av.x + av.y + av.z + av.w;

#if __CUDA_ARCH__ >= 900
    cudaGridDependencySynchronize();
#endif

    const float4 e4 = *(reinterpret_cast<const float4*>(g_e + (size_t)b * NN) + t);
    float se = e4.x + e4.y + e4.z + e4.w;

    se = warp_sum(se);
    sa = warp_sum(sa);
    if (lane == 0) { s_e[warp] = se; s_a[warp] = sa; }
    __syncthreads();
    if (t == 0) {
        float esum = 0.f, asum = 0.f;
#pragma unroll
        for (int i = 0; i < 8; i++) { esum += s_e[i]; asum += s_a[i]; }
        const float s0 = wg * ag;                       // alloc coefficient
        const float s1 = wg * (1.f - ag) / esum;        // e coefficient
        const float wsum = wg * (ag * asum + (1.f - ag));
        g_scal[b] = make_float4(s0, s1, 1.f - wsum, 0.f);
    }
}

// Phase 3: link update with on-the-fly w. 4 rows/block.
// w_j = s0*alloc_j + s1*e_j ; link = (1-wi-wj)*L + wi*pj ; diag=0.
// Blocks with i0==0 additionally write out_w[b,:] and out_prec[b,:].
__global__ __launch_bounds__(256) void wh_link_kernel(
    const float* __restrict__ L, const float* __restrict__ alloc,
    const float* __restrict__ p, float* __restrict__ out,
    float* __restrict__ out_w, float* __restrict__ out_prec)
{
    const size_t row0 = (size_t)blockIdx.x * 4;   // b*N + i0
    const int b = (int)(row0 >> 10);
    const int i0 = (int)(row0 & 1023);
    const int j4 = threadIdx.x;

    // independent loads first: 256MB L stream + p + alloc broadcasts
    float4 l[4];
#pragma unroll
    for (int r = 0; r < 4; r++)
        l[r] = __ldcs(reinterpret_cast<const float4*>(L) + (row0 + r) * 256 + j4);
    const float4 pj = __ldg(reinterpret_cast<const float4*>(p) + (size_t)b * 256 + j4);
    const float4 aj = __ldg(reinterpret_cast<const float4*>(alloc) + (size_t)b * 256 + j4);
    float ai[4];
#pragma unroll
    for (int r = 0; r < 4; r++) ai[r] = __ldg(alloc + row0 + r);

#if __CUDA_ARCH__ >= 900
    cudaGridDependencySynchronize();
#endif

    const float4 sc = g_scal[b];      // {s0, s1, 1-wsum, _}
    const float4 ej = *(reinterpret_cast<const float4*>(g_e + (size_t)b * NN) + j4);

    float4 wj;
    wj.x = sc.x * aj.x + sc.y * ej.x;
    wj.y = sc.x * aj.y + sc.y * ej.y;
    wj.z = sc.x * aj.z + sc.y * ej.z;
    wj.w = sc.x * aj.w + sc.y * ej.w;

    float wi[4];
#pragma unroll
    for (int r = 0; r < 4; r++)
        wi[r] = sc.x * ai[r] + sc.y * g_e[row0 + r];

#pragma unroll
    for (int r = 0; r < 4; r++) {
        float4 o;
        o.x = (1.f - wi[r] - wj.x) * l[r].x + wi[r] * pj.x;
        o.y = (1.f - wi[r] - wj.y) * l[r].y + wi[r] * pj.y;
        o.z = (1.f - wi[r] - wj.z) * l[r].z + wi[r] * pj.z;
        o.w = (1.f - wi[r] - wj.w) * l[r].w + wi[r] * pj.w;

        const int i = i0 + r;
        if (j4 == (i >> 2)) ((float*)&o)[i & 3] = 0.f;

        __stcs(reinterpret_cast<float4*>(out) + (row0 + r) * 256 + j4, o);
    }

    // one block per batch emits w_weights and precedence_new
    if (i0 == 0) {
        reinterpret_cast<float4*>(out_w + (size_t)b * NN)[j4] = wj;
        float4 pn;
        pn.x = sc.z * pj.x + wj.x;
        pn.y = sc.z * pj.y + wj.y;
        pn.z = sc.z * pj.z + wj.z;
        pn.w = sc.z * pj.w + wj.w;
        reinterpret_cast<float4*>(out_prec + (size_t)b * NN)[j4] = pn;
    }
}

static inline void launch_pdl(void* fn, dim3 grid, dim3 block, void** args,
                              cudaStream_t stream)
{
    cudaLaunchAttribute attr[1];
    attr[0].id = cudaLaunchAttributeProgrammaticStreamSerialization;
    attr[0].val.programmaticStreamSerializationAllowed = 1;

    cudaLaunchConfig_t cfg = {};
    cfg.gridDim = grid;
    cfg.blockDim = block;
    cfg.dynamicSmemBytes = 0;
    cfg.stream = stream;
    cfg.attrs = attr;
    cfg.numAttrs = 1;
    cudaLaunchKernelExC(&cfg, fn, args);
}

extern "C" void kernel_launch(void* const* d_in, const int* in_sizes, int n_in,
                              void* d_out, int out_size)
{
    const float* w_key  = (const float*)d_in[0];
    const float* w_beta = (const float*)d_in[1];
    // d_in[2] = e_vector (unused), d_in[3] = w_vector (unused)
    const float* a_gate = (const float*)d_in[4];
    const float* w_gate = (const float*)d_in[5];
    const float* alloc  = (const float*)d_in[6];
    const float* memory = (const float*)d_in[7];
    const float* linkm  = (const float*)d_in[8];
    const float* prec   = (const float*)d_in[9];

    float* out = (float*)d_out;
    float* out_w    = out;                                   // B*N
    float* out_mem  = out + (size_t)BB * NN;                 // B*N*W
    float* out_link = out_mem + (size_t)BB * NN * WW;        // B*N*N
    float* out_prec = out_link + (size_t)BB * NN * NN;       // B*N

    cudaStream_t s = 0;

    wh_sim_kernel<<<SIM_BLOCKS, 256, 0, s>>>(w_key, w_beta, memory, out_mem);

    {
        void* args[] = { (void*)&a_gate, (void*)&w_gate, (void*)&alloc };
        launch_pdl((void*)wh_scal_kernel, dim3(BB), dim3(256), args, s);
    }
    {
        void* args[] = { (void*)&linkm, (void*)&alloc, (void*)&prec,
                         (void*)&out_link, (void*)&out_w, (void*)&out_prec };
        launch_pdl((void*)wh_link_kernel, dim3(BB * NN / 4), dim3(256), args, s);
    }
}

// round 17
// speedup vs baseline: 1.4224x; 1.0194x over previous
#include <cuda_runtime.h>
#include <math.h>

#define EPSF 1e-8f
#define BB 64
#define NN 1024
#define WW 128

__device__ float  g_e[BB * NN];    // scratch: exp(beta * cosine)
__device__ float4 g_scal[BB];      // per-batch {wg*ag, wg*(1-ag)/esum, 1-wsum, 0}

__device__ __forceinline__ float warp_sum(float v) {
#pragma unroll
    for (int o = 16; o; o >>= 1) v += __shfl_xor_sync(0xffffffffu, v, o);
    return v;
}

// Phase 1: e = exp(beta * cosine) + memory passthrough AFTER early trigger.
// R10 body (4 rows/warp, 8 warps/block, grid=2048, 32 regs) through the g_e
// store; then trigger PDL so scal/link launch while this kernel's passthrough
// store tail overlaps their DRAM streams. m[] is re-loaded from L1 after the
// trigger so no float4 values stay live across it (R5's register bug).
__global__ __launch_bounds__(256) void wh_sim_kernel(
    const float* __restrict__ w_key, const float* __restrict__ w_beta,
    const float* __restrict__ memory, float* __restrict__ out_mem)
{
    const int t = threadIdx.x;
    const int lane = t & 31;
    const int warp = t >> 5;
    const size_t row0 = ((size_t)blockIdx.x * 8 + warp) * 4;  // first of 4 rows
    const int b = (int)(row0 >> 10);
    const unsigned FULL = 0xffffffffu;

    const float4 k4 = __ldg(reinterpret_cast<const float4*>(w_key + b * WW) + lane);
    float ks = k4.x * k4.x + k4.y * k4.y + k4.z * k4.z + k4.w * k4.w;
    ks = warp_sum(ks);
    const float knorm = sqrtf(ks) + EPSF;

    const float bx = __ldg(w_beta + b);
    const float beta = 1.f + (bx > 20.f ? bx : log1pf(expf(bx)));

    float4 m[4];
#pragma unroll
    for (int r = 0; r < 4; r++)
        m[r] = reinterpret_cast<const float4*>(memory + (row0 + r) * WW)[lane];

    float dot[4], sq[4];
#pragma unroll
    for (int r = 0; r < 4; r++) {
        dot[r] = m[r].x * k4.x + m[r].y * k4.y + m[r].z * k4.z + m[r].w * k4.w;
        sq[r]  = m[r].x * m[r].x + m[r].y * m[r].y + m[r].z * m[r].z + m[r].w * m[r].w;
    }

    // ---- tree-merge reduction: 8 values -> lane-indexed sums (17 SHFLs) ----
    const bool lo16 = (lane & 16) == 0;
    float A[4];
#pragma unroll
    for (int r = 0; r < 4; r++) {
        float dx = __shfl_xor_sync(FULL, dot[r], 16);
        float sx = __shfl_xor_sync(FULL, sq[r], 16);
        A[r] = lo16 ? (dot[r] + dx) : (sq[r] + sx);
    }
    const bool lo8 = (lane & 8) == 0;
    float a0 = __shfl_xor_sync(FULL, A[0], 8);
    float a1 = __shfl_xor_sync(FULL, A[1], 8);
    float B0 = lo8 ? (A[0] + a0) : (A[1] + a1);
    float a2 = __shfl_xor_sync(FULL, A[2], 8);
    float a3 = __shfl_xor_sync(FULL, A[3], 8);
    float B1 = lo8 ? (A[2] + a2) : (A[3] + a3);
    const bool lo4 = (lane & 4) == 0;
    float b0 = __shfl_xor_sync(FULL, B0, 4);
    float b1 = __shfl_xor_sync(FULL, B1, 4);
    float C = lo4 ? (B0 + b0) : (B1 + b1);
    C += __shfl_xor_sync(FULL, C, 2);
    C += __shfl_xor_sync(FULL, C, 1);
    const float sqv = __shfl_xor_sync(FULL, C, 16);

    // lanes 0,4,8,12 hold dot for r = ((lane&4)?2:0) + ((lane&8)?1:0)
    if ((lane & 19) == 0) {
        const int r = ((lane & 4) ? 2 : 0) + ((lane & 8) ? 1 : 0);
        const float sim = beta * C / ((sqrtf(sqv) + EPSF) * knorm);
        g_e[row0 + r] = expf(sim);   // no-max softmax numerator (|sim| small)
    }

    // g_e done for this block: release dependents while we finish the copy.
#if __CUDA_ARCH__ >= 900
    cudaTriggerProgrammaticLaunchCompletion();
#endif
    asm volatile("" ::: "memory");   // pin reloads below the trigger

    // passthrough copy: re-load rows (L1-hot: just read above) and store.
#pragma unroll
    for (int r = 0; r < 4; r++) {
        const float4 m2 = reinterpret_cast<const float4*>(memory + (row0 + r) * WW)[lane];
        __stcs(reinterpret_cast<float4*>(out_mem + (row0 + r) * WW) + lane, m2);
    }
}

// Phase 2: per-batch scalar reduction. 64 blocks x 256 threads.
// Emits {wg*ag, wg*(1-ag)/esum, 1 - wsum} with wsum = wg*(ag*S_alloc + (1-ag)).
__global__ __launch_bounds__(256) void wh_scal_kernel(
    const float* __restrict__ a_gate, const float* __restrict__ w_gate,
    const float* __restrict__ alloc)
{
    const int b = blockIdx.x;
    const int t = threadIdx.x;
    const int lane = t & 31;
    const int warp = t >> 5;
    __shared__ float s_e[8], s_a[8];

    // independent inputs before grid-dep sync
    const float wg = 1.f / (1.f + expf(-w_gate[b]));
    const float ag = 1.f / (1.f + expf(-a_gate[b]));
    const float4 av = __ldg(reinterpret_cast<const float4*>(alloc + (size_t)b * NN) + t);
    float sa = av.x + av.y + av.z + av.w;

#if __CUDA_ARCH__ >= 900
    cudaGridDependencySynchronize();
#endif

    const float4 e4 = *(reinterpret_cast<const float4*>(g_e + (size_t)b * NN) + t);
    float se = e4.x + e4.y + e4.z + e4.w;

    se = warp_sum(se);
    sa = warp_sum(sa);
    if (lane == 0) { s_e[warp] = se; s_a[warp] = sa; }
    __syncthreads();
    if (t == 0) {
        float esum = 0.f, asum = 0.f;
#pragma unroll
        for (int i = 0; i < 8; i++) { esum += s_e[i]; asum += s_a[i]; }
        const float s0 = wg * ag;                       // alloc coefficient
        const float s1 = wg * (1.f - ag) / esum;        // e coefficient
        const float wsum = wg * (ag * asum + (1.f - ag));
        g_scal[b] = make_float4(s0, s1, 1.f - wsum, 0.f);
    }
}

// Phase 3: link update with on-the-fly w. 4 rows/block.
// w_j = s0*alloc_j + s1*e_j ; link = (1-wi-wj)*L + wi*pj ; diag=0.
// Blocks with i0==0 additionally write out_w[b,:] and out_prec[b,:].
__global__ __launch_bounds__(256) void wh_link_kernel(
    const float* __restrict__ L, const float* __restrict__ alloc,
    const float* __restrict__ p, float* __restrict__ out,
    float* __restrict__ out_w, float* __restrict__ out_prec)
{
    const size_t row0 = (size_t)blockIdx.x * 4;   // b*N + i0
    const int b = (int)(row0 >> 10);
    const int i0 = (int)(row0 & 1023);
    const int j4 = threadIdx.x;

    // independent loads first: 256MB L stream + p + alloc broadcasts
    float4 l[4];
#pragma unroll
    for (int r = 0; r < 4; r++)
        l[r] = __ldcs(reinterpret_cast<const float4*>(L) + (row0 + r) * 256 + j4);
    const float4 pj = __ldg(reinterpret_cast<const float4*>(p) + (size_t)b * 256 + j4);
    const float4 aj = __ldg(reinterpret_cast<const float4*>(alloc) + (size_t)b * 256 + j4);
    float ai[4];
#pragma unroll
    for (int r = 0; r < 4; r++) ai[r] = __ldg(alloc + row0 + r);

#if __CUDA_ARCH__ >= 900
    cudaGridDependencySynchronize();
#endif

    const float4 sc = g_scal[b];      // {s0, s1, 1-wsum, _}
    const float4 ej = *(reinterpret_cast<const float4*>(g_e + (size_t)b * NN) + j4);

    float4 wj;
    wj.x = sc.x * aj.x + sc.y * ej.x;
    wj.y = sc.x * aj.y + sc.y * ej.y;
    wj.z = sc.x * aj.z + sc.y * ej.z;
    wj.w = sc.x * aj.w + sc.y * ej.w;

    float wi[4];
#pragma unroll
    for (int r = 0; r < 4; r++)
        wi[r] = sc.x * ai[r] + sc.y * g_e[row0 + r];

#pragma unroll
    for (int r = 0; r < 4; r++) {
        float4 o;
        o.x = (1.f - wi[r] - wj.x) * l[r].x + wi[r] * pj.x;
        o.y = (1.f - wi[r] - wj.y) * l[r].y + wi[r] * pj.y;
        o.z = (1.f - wi[r] - wj.z) * l[r].z + wi[r] * pj.z;
        o.w = (1.f - wi[r] - wj.w) * l[r].w + wi[r] * pj.w;

        const int i = i0 + r;
        if (j4 == (i >> 2)) ((float*)&o)[i & 3] = 0.f;

        __stcs(reinterpret_cast<float4*>(out) + (row0 + r) * 256 + j4, o);
    }

    // one block per batch emits w_weights and precedence_new
    if (i0 == 0) {
        reinterpret_cast<float4*>(out_w + (size_t)b * NN)[j4] = wj;
        float4 pn;
        pn.x = sc.z * pj.x + wj.x;
        pn.y = sc.z * pj.y + wj.y;
        pn.z = sc.z * pj.z + wj.z;
        pn.w = sc.z * pj.w + wj.w;
        reinterpret_cast<float4*>(out_prec + (size_t)b * NN)[j4] = pn;
    }
}

static inline void launch_pdl(void* fn, dim3 grid, dim3 block, void** args,
                              cudaStream_t stream)
{
    cudaLaunchAttribute attr[1];
    attr[0].id = cudaLaunchAttributeProgrammaticStreamSerialization;
    attr[0].val.programmaticStreamSerializationAllowed = 1;

    cudaLaunchConfig_t cfg = {};
    cfg.gridDim = grid;
    cfg.blockDim = block;
    cfg.dynamicSmemBytes = 0;
    cfg.stream = stream;
    cfg.attrs = attr;
    cfg.numAttrs = 1;
    cudaLaunchKernelExC(&cfg, fn, args);
}

extern "C" void kernel_launch(void* const* d_in, const int* in_sizes, int n_in,
                              void* d_out, int out_size)
{
    const float* w_key  = (const float*)d_in[0];
    const float* w_beta = (const float*)d_in[1];
    // d_in[2] = e_vector (unused), d_in[3] = w_vector (unused)
    const float* a_gate = (const float*)d_in[4];
    const float* w_gate = (const float*)d_in[5];
    const float* alloc  = (const float*)d_in[6];
    const float* memory = (const float*)d_in[7];
    const float* linkm  = (const float*)d_in[8];
    const float* prec   = (const float*)d_in[9];

    float* out = (float*)d_out;
    float* out_w    = out;                                   // B*N
    float* out_mem  = out + (size_t)BB * NN;                 // B*N*W
    float* out_link = out_mem + (size_t)BB * NN * WW;        // B*N*N
    float* out_prec = out_link + (size_t)BB * NN * NN;       // B*N

    cudaStream_t s = 0;

    wh_sim_kernel<<<BB * NN / 32, 256, 0, s>>>(w_key, w_beta, memory, out_mem);

    {
        void* args[] = { (void*)&a_gate, (void*)&w_gate, (void*)&alloc };
        launch_pdl((void*)wh_scal_kernel, dim3(BB), dim3(256), args, s);
    }
    {
        void* args[] = { (void*)&linkm, (void*)&alloc, (void*)&prec,
                         (void*)&out_link, (void*)&out_w, (void*)&out_prec };
        launch_pdl((void*)wh_link_kernel, dim3(BB * NN / 4), dim3(256), args, s);
    }
}